// round 3
// baseline (speedup 1.0000x reference)
#include <cuda_runtime.h>
#include <cuda_bf16.h>

// JointBilateral upsample, S=4, K=5. One thread = 4 horizontal output pixels
// (w = 4q..4q+3). All share first tap guidance column 4q+1, tap row 4p+1.
// Second row tap iff h%4==3 && h<=507; second col tap only for r=3 pixel, q<127.
// Second-column tap values == next lane's first-tap values -> shuffle.
//
// e(tap) = exp(-0.125*||g_tap - g_ctr||^2) * exp(-0.005*((i-2)^2+(j-2)^2))
// out = sum(e * wgt[4-i][4-j] * x_tap) / sum(e)

#define CH  (512 * 512)
#define E1  0.9950124791926823f   /* exp(-0.005) */
#define E4  0.9801986733067553f   /* exp(-0.020) */

__global__ void __launch_bounds__(256, 6) jb_kernel(
    const float* __restrict__ x,
    const float* __restrict__ g,
    const float* __restrict__ wgt,
    float* __restrict__ out)
{
    int idx  = blockIdx.x * 256 + threadIdx.x;   // 262144 threads
    int lane = threadIdx.x & 31;
    int q = idx & 127;
    int h = (idx >> 7) & 511;
    int b = idx >> 16;

    const float* gb = g + (size_t)b * 3 * CH;
    const float* xb = x + b * (128 * 128);

    int w0 = q << 2;
    int p  = h >> 2;
    int s  = h & 3;
    bool row2 = (s == 3) && (p < 127);
    bool col2 = (q < 127);

    int oc  = h * 512 + w0;
    int o00 = (4 * p + 1) * 512 + (4 * q + 1);

    // ---- all loads up front ----
    float4 c0 = *(const float4*)(gb + oc);
    float4 c1 = *(const float4*)(gb + CH + oc);
    float4 c2 = *(const float4*)(gb + 2 * CH + oc);

    float t000 = gb[o00];
    float t001 = gb[o00 + CH];
    float t002 = gb[o00 + 2 * CH];
    float x00  = xb[p * 128 + q];

    float t100 = 0.f, t101 = 0.f, t102 = 0.f, x10 = 0.f;
    if (row2) {                      // warp-uniform branch
        t100 = gb[o00 + 4 * 512];
        t101 = gb[o00 + 4 * 512 + CH];
        t102 = gb[o00 + 4 * 512 + 2 * CH];
        x10  = xb[(p + 1) * 128 + q];
    }

    // weights (warp-uniform addresses)
    const float* wr = wgt + (s + 1) * 5;
    float wr0 = wr[0];
    float wa0 = wr[1], wa1 = wr[2], wa2 = wr[3], wa3 = wr[4];
    float v0 = 0.f, vb0 = 0.f, vb1 = 0.f, vb2 = 0.f, vb3 = 0.f;
    if (row2) {
        v0 = wgt[0]; vb0 = wgt[1]; vb1 = wgt[2]; vb2 = wgt[3]; vb3 = wgt[4];
    }

    // ---- second-col taps via shuffle (next lane's first-tap values) ----
    unsigned full = 0xffffffffu;
    float t010 = __shfl_down_sync(full, t000, 1);
    float t011 = __shfl_down_sync(full, t001, 1);
    float t012 = __shfl_down_sync(full, t002, 1);
    float x01  = __shfl_down_sync(full, x00, 1);
    float t110 = __shfl_down_sync(full, t100, 1);
    float t111 = __shfl_down_sync(full, t101, 1);
    float t112 = __shfl_down_sync(full, t102, 1);
    float x11  = __shfl_down_sync(full, x10, 1);
    if (lane == 31 && col2) {        // only 3 warps' lane-31 actually load
        t010 = gb[o00 + 4];
        t011 = gb[o00 + 4 + CH];
        t012 = gb[o00 + 4 + 2 * CH];
        x01  = xb[p * 128 + q + 1];
        if (row2) {
            t110 = gb[o00 + 4 * 512 + 4];
            t111 = gb[o00 + 4 * 512 + 4 + CH];
            t112 = gb[o00 + 4 * 512 + 4 + 2 * CH];
            x11  = xb[(p + 1) * 128 + q + 1];
        }
    }

    // fold weight * x products (register savers)
    float wx0 = wa0 * x00, wx1 = wa1 * x00, wx2 = wa2 * x00, wx3 = wa3 * x00;
    float vx0 = vb0 * x10, vx1 = vb1 * x10, vx2 = vb2 * x10, vx3 = vb3 * x10;
    float wr0x = wr0 * x01;
    float v0x  = v0 * x11;

    // spatial factor for first tap row: (i0-2)^2 = {1,0,1,4} for s=0..3
    float espR0 = (s == 1) ? 1.0f : ((s == 3) ? E4 : E1);
    // premultiplied per-r first-row factors
    float em0 = espR0 * E1, em1 = espR0, em2 = espR0 * E1, em3 = espR0 * E4;

    float ctr0[4] = {c0.x, c0.y, c0.z, c0.w};
    float ctr1[4] = {c1.x, c1.y, c1.z, c1.w};
    float ctr2[4] = {c2.x, c2.y, c2.z, c2.w};
    float emr[4]  = {em0, em1, em2, em3};
    float wxr[4]  = {wx0, wx1, wx2, wx3};
    float vxr[4]  = {vx0, vx1, vx2, vx3};
    const float es2[4] = {E4 * E1, E4, E4 * E1, E4 * E4}; // E4*espC[r]

    float res[4];
#pragma unroll
    for (int r = 0; r < 4; r++) {
        float d0 = t000 - ctr0[r];
        float d1 = t001 - ctr1[r];
        float d2 = t002 - ctr2[r];
        float e  = __expf(-0.125f * (d0 * d0 + d1 * d1 + d2 * d2)) * emr[r];
        float n  = e;
        float a  = e * wxr[r];

        if (row2) {
            float f0 = t100 - ctr0[r];
            float f1 = t101 - ctr1[r];
            float f2 = t102 - ctr2[r];
            float e2 = __expf(-0.125f * (f0 * f0 + f1 * f1 + f2 * f2)) * es2[r];
            n += e2;
            a += e2 * vxr[r];
        }
        if (r == 3 && col2) {
            float h0 = t010 - ctr0[r];
            float h1 = t011 - ctr1[r];
            float h2 = t012 - ctr2[r];
            float e3 = __expf(-0.125f * (h0 * h0 + h1 * h1 + h2 * h2)) * (espR0 * E4);
            n += e3;
            a += e3 * wr0x;
            if (row2) {
                float k0 = t110 - ctr0[r];
                float k1 = t111 - ctr1[r];
                float k2 = t112 - ctr2[r];
                float e4 = __expf(-0.125f * (k0 * k0 + k1 * k1 + k2 * k2)) * (E4 * E4);
                n += e4;
                a += e4 * v0x;
            }
        }
        res[r] = __fdividef(a, n);
    }

    *(float4*)(out + (size_t)idx * 4) = make_float4(res[0], res[1], res[2], res[3]);
}

extern "C" void kernel_launch(void* const* d_in, const int* in_sizes, int n_in,
                              void* d_out, int out_size)
{
    const float* x   = (const float*)d_in[0];
    const float* g   = (const float*)d_in[1];
    const float* wgt = (const float*)d_in[2];
    float* out = (float*)d_out;

    int total_threads = out_size / 4;     // 262144
    jb_kernel<<<total_threads / 256, 256>>>(x, g, wgt, out);
}

// round 4
// speedup vs baseline: 1.3092x; 1.3092x over previous
#include <cuda_runtime.h>
#include <cuda_bf16.h>

// JointBilateral upsample, S=4, K=5. One thread = one 4x4 aligned output block
// (rows 4p..4p+3, cols 4q..4q+3). All 16 pixels share the single first tap at
// guidance point (4p+1, 4q+1); extra taps: right col tap (4q+5) for r=3 pixels
// iff q<127, down row tap (4p+5) for s=3 pixels iff p<127, corner for (3,3).
//
// e(tap) = exp(-0.125*||g_tap - g_ctr||^2) * exp(-0.005*((i-2)^2+(j-2)^2))
// out = sum(e * wgt[4-i][4-j] * x_tap) / sum(e)
// First tap (row s, col r): spatial (1-s)^2+(1-r)^2, weight wgt[s+1][r+1].
// Extra taps have (i-2)^2 = 4 (factor E4) and weight row/col index 0.

#define CH  (512 * 512)
#define E1  0.9950124791926823f   /* exp(-0.005) */
#define E4  0.9801986733067553f   /* exp(-0.020) */

__global__ void __launch_bounds__(128) jb_kernel(
    const float* __restrict__ x,
    const float* __restrict__ g,
    const float* __restrict__ wgt,
    float* __restrict__ out)
{
    int idx = blockIdx.x * 128 + threadIdx.x;   // 65536 threads
    int q = idx & 127;
    int p = (idx >> 7) & 127;
    int b = idx >> 14;

    const float* gb = g + (size_t)b * 3 * CH;
    const float* xb = x + b * (128 * 128);
    float* ob = out + (size_t)b * CH;

    bool col2 = (q < 127);
    bool row2 = (p < 127);
    int dq = col2 ? 4 : 0;          // clamped offsets: loads always safe
    int dr = row2 ? 4 * 512 : 0;
    int cq = col2 ? 1 : 0;
    int cp = row2 ? 1 : 0;

    int o00 = (4 * p + 1) * 512 + (4 * q + 1);

    // ---- tap guidance (12 scalars) + low-res x (4 scalars), front-loaded ----
    float t0 = gb[o00];             float t1 = gb[o00 + CH];           float t2 = gb[o00 + 2 * CH];
    float u0 = gb[o00 + dq];        float u1 = gb[o00 + dq + CH];      float u2 = gb[o00 + dq + 2 * CH];
    float v0 = gb[o00 + dr];        float v1 = gb[o00 + dr + CH];      float v2 = gb[o00 + dr + 2 * CH];
    float z0 = gb[o00 + dr + dq];   float z1 = gb[o00 + dr + dq + CH]; float z2 = gb[o00 + dr + dq + 2 * CH];

    int xo = p * 128 + q;
    float x00 = xb[xo];
    float x01 = xb[xo + cq];
    float x10 = xb[xo + cp * 128];
    float x11 = xb[xo + cp * 128 + cq];

    // spatial factors per col r for first taps: (1-r)^2 -> {E1,1,E1,E4}
    const float espC[4] = {E1, 1.0f, E1, E4};

#pragma unroll
    for (int s = 0; s < 4; s++) {
        int hrow = (4 * p + s) * 512 + 4 * q;
        float4 c0 = *(const float4*)(gb + hrow);
        float4 c1 = *(const float4*)(gb + CH + hrow);
        float4 c2 = *(const float4*)(gb + 2 * CH + hrow);
        float ctr0[4] = {c0.x, c0.y, c0.z, c0.w};
        float ctr1[4] = {c1.x, c1.y, c1.z, c1.w};
        float ctr2[4] = {c2.x, c2.y, c2.z, c2.w};

        const float espS = (s == 1) ? 1.0f : ((s == 3) ? E4 : E1);

        // per-row weights (warp-uniform, L1-resident)
        float wA0 = wgt[(s + 1) * 5 + 1] * x00;
        float wA1 = wgt[(s + 1) * 5 + 2] * x00;
        float wA2 = wgt[(s + 1) * 5 + 3] * x00;
        float wA3 = wgt[(s + 1) * 5 + 4] * x00;
        float wAr[4] = {wA0, wA1, wA2, wA3};
        float wCol = wgt[(s + 1) * 5] * x01;          // second-col weight*x

        float res[4];
#pragma unroll
        for (int r = 0; r < 4; r++) {
            float d0 = t0 - ctr0[r];
            float d1 = t1 - ctr1[r];
            float d2 = t2 - ctr2[r];
            float e = __expf(-0.125f * (d0 * d0 + d1 * d1 + d2 * d2)) * (espS * espC[r]);
            float n = e;
            float a = e * wAr[r];

            if (s == 3 && row2) {               // second row tap
                float f0 = v0 - ctr0[r];
                float f1 = v1 - ctr1[r];
                float f2 = v2 - ctr2[r];
                float e2 = __expf(-0.125f * (f0 * f0 + f1 * f1 + f2 * f2)) * (E4 * espC[r]);
                n += e2;
                a += e2 * wgt[r + 1] * x10;
            }
            if (r == 3 && col2) {               // second col tap
                float h0 = u0 - ctr0[r];
                float h1 = u1 - ctr1[r];
                float h2 = u2 - ctr2[r];
                float e3 = __expf(-0.125f * (h0 * h0 + h1 * h1 + h2 * h2)) * (espS * E4);
                n += e3;
                a += e3 * wCol;
                if (s == 3 && row2) {           // corner tap
                    float k0 = z0 - ctr0[r];
                    float k1 = z1 - ctr1[r];
                    float k2 = z2 - ctr2[r];
                    float e4 = __expf(-0.125f * (k0 * k0 + k1 * k1 + k2 * k2)) * (E4 * E4);
                    n += e4;
                    a += e4 * wgt[0] * x11;
                }
            }
            res[r] = __fdividef(a, n);
        }
        *(float4*)(ob + hrow) = make_float4(res[0], res[1], res[2], res[3]);
    }
}

extern "C" void kernel_launch(void* const* d_in, const int* in_sizes, int n_in,
                              void* d_out, int out_size)
{
    const float* x   = (const float*)d_in[0];
    const float* g   = (const float*)d_in[1];
    const float* wgt = (const float*)d_in[2];
    float* out = (float*)d_out;

    int total_threads = out_size / 16;    // 65536
    jb_kernel<<<total_threads / 128, 128>>>(x, g, wgt, out);
}